// round 13
// baseline (speedup 1.0000x reference)
#include <cuda_runtime.h>
#include <cuda_bf16.h>

#define MAXN 300000
#define BR   128                 // rows per block
#define XTS  160                 // xT k-row stride (>= 128 + max swizzle 28)
#define KSWZ(k) ((((k) >> 3) & 7) * 4)   // bank swizzle per k-row

__device__ float d_g[MAXN * 64];
__device__ float d_s[MAXN * 64];
__device__ float d_deg[MAXN];
__device__ float d_dinv[MAXN];

// ---------------------------------------------------------------------------
__global__ void deg_init_kernel(float* deg, int n) {
    int i = blockIdx.x * blockDim.x + threadIdx.x;
    if (i < n) deg[i] = 1.0f;
}
__global__ void deg_count_kernel(const int* __restrict__ col, float* deg, int e) {
    int i = blockIdx.x * blockDim.x + threadIdx.x;
    if (i < e) atomicAdd(&deg[col[i]], 1.0f);
}
__global__ void dinv_kernel(const float* __restrict__ deg, float* dinv, int n) {
    int i = blockIdx.x * blockDim.x + threadIdx.x;
    if (i < n) dinv[i] = rsqrtf(deg[i]);
}

// ---------------------------------------------------------------------------
#define FFMA2(acc, x, w) \
    asm volatile("fma.rn.f32x2 %0, %1, %2, %0;" : "+l"(acc) : "l"(x), "l"(w))

union F4U   { float4 f4; unsigned long long u[2]; };
union ULLF2 { unsigned long long u; float2 f; };

// Fused transform + GEMM + epilogue, f32x2 over ROW pairs.
//  MODE 0: x = embedding gather; MODE 1: x = relu(dinv*s+b); MODE 2: final.
// Block: 128 rows x 64 cols, 256 threads. Thread tile 8 rows x 4 cols.
// Warp shape: 4 rowq-groups x 8 colq-groups  ->  min crossbar traffic.
// smem: xT[64][XTS] (transposed, k-swizzled) ; Wd[64][64] dup W as float2.
#define SMEM_FLOATS (64 * XTS + 64 * 128)

template <int MODE>
__global__ void __launch_bounds__(256, 3)
mm5_kernel(const float* __restrict__ xsrcA,
           const float* __restrict__ xsrcB,
           const int*   __restrict__ uids,
           const int*   __restrict__ iids,
           const float* __restrict__ dinv,
           const float* __restrict__ bprev,
           const float* __restrict__ W,
           const float* __restrict__ bout,
           float* __restrict__ g,
           float* __restrict__ s,
           float* __restrict__ out,
           int N, int U)
{
    extern __shared__ float smem[];
    float* xT = smem;             // xT[k*XTS + KSWZ(k) + row]
    float* Wd = smem + 64 * XTS;  // Wd[k*128 + c*2] = (w,w)

    const int t  = threadIdx.x;
    const int r0 = blockIdx.x * BR;

    // --- Wd fill: duplicate each W scalar into a float2 ---
    #pragma unroll
    for (int idx = t; idx < 64 * 64; idx += 256) {
        int k = idx >> 6, c = idx & 63;
        float w = __ldg(&W[idx]);
        *(float2*)&Wd[k * 128 + c * 2] = make_float2(w, w);
    }

    // --- xT fill: coalesced row loads, transposed swizzled stores ---
    #pragma unroll
    for (int idx = t; idx < BR * 16; idx += 256) {
        int rr  = idx >> 4;          // 0..127
        int kq  = idx & 15;          // float4 index along k
        int row = r0 + rr;
        float4 v = make_float4(0.f, 0.f, 0.f, 0.f);
        if (row < N) {
            if (MODE == 0) {
                const float* src = (row < U)
                    ? &xsrcA[(long)__ldg(&uids[row]) * 64 + kq * 4]
                    : &xsrcB[(long)__ldg(&iids[row - U]) * 64 + kq * 4];
                v = *(const float4*)src;
            } else {
                float di  = __ldg(&dinv[row]);
                float4 sv = *(const float4*)&xsrcA[(long)row * 64 + kq * 4];
                float4 bv = *(const float4*)&bprev[kq * 4];
                v.x = di * sv.x + bv.x;  v.y = di * sv.y + bv.y;
                v.z = di * sv.z + bv.z;  v.w = di * sv.w + bv.w;
                if (MODE == 1) {
                    v.x = fmaxf(v.x, 0.f); v.y = fmaxf(v.y, 0.f);
                    v.z = fmaxf(v.z, 0.f); v.w = fmaxf(v.w, 0.f);
                }
            }
        }
        int k0 = 4 * kq;
        xT[(k0 + 0) * XTS + KSWZ(k0 + 0) + rr] = v.x;
        xT[(k0 + 1) * XTS + KSWZ(k0 + 1) + rr] = v.y;
        xT[(k0 + 2) * XTS + KSWZ(k0 + 2) + rr] = v.z;
        xT[(k0 + 3) * XTS + KSWZ(k0 + 3) + rr] = v.w;
    }
    __syncthreads();

    // Warp-optimal mapping: warp covers 4 rowq x 8 colq.
    const int lane = t & 31;
    const int wid  = t >> 5;
    const int rowq = (wid & 3) * 4 + (lane >> 3);   // 0..15 -> rows rowq*8..+7
    const int colq = (wid >> 2) * 8 + (lane & 7);   // 0..15 -> cols 2*colq(+1), +32

    const float* xbase = &xT[rowq * 8];
    const float* wbase = &Wd[colq * 4];

    unsigned long long acc[4][4];   // [rowpair][col: 2c,2c+1,2c+32,2c+33]
    #pragma unroll
    for (int i = 0; i < 4; i++)
        #pragma unroll
        for (int j = 0; j < 4; j++) acc[i][j] = 0ull;

    #pragma unroll 4
    for (int k = 0; k < 64; k++) {
        F4U xa, xb, w0, w1;
        xa.f4 = *(const float4*)(xbase + k * XTS + KSWZ(k));      // rows +0..3
        xb.f4 = *(const float4*)(xbase + k * XTS + KSWZ(k) + 4);  // rows +4..7
        w0.f4 = *(const float4*)(wbase + k * 128);        // cols 2c,2c+1 dup
        w1.f4 = *(const float4*)(wbase + k * 128 + 64);   // cols 2c+32,+33 dup
        unsigned long long xp[4] = { xa.u[0], xa.u[1], xb.u[0], xb.u[1] };
        unsigned long long wp[4] = { w0.u[0], w0.u[1], w1.u[0], w1.u[1] };
        #pragma unroll
        for (int rp = 0; rp < 4; rp++) {
            FFMA2(acc[rp][0], xp[rp], wp[0]);
            FFMA2(acc[rp][1], xp[rp], wp[1]);
            FFMA2(acc[rp][2], xp[rp], wp[2]);
            FFMA2(acc[rp][3], xp[rp], wp[3]);
        }
    }

    // --- epilogue ---
    #pragma unroll
    for (int rp = 0; rp < 4; rp++) {
        int row0 = r0 + rowq * 8 + rp * 2;
        int row1 = row0 + 1;
        float d0 = 0.f, d1 = 0.f;
        if (MODE != 2) {
            if (row0 < N) d0 = dinv[row0];
            if (row1 < N) d1 = dinv[row1];
        }
        #pragma unroll
        for (int m = 0; m < 2; m++) {
            ULLF2 a0, a1;
            a0.u = acc[rp][2 * m];
            a1.u = acc[rp][2 * m + 1];
            int c = 2 * colq + 32 * m;
            if (MODE == 2) {
                float bx = bout[c], by = bout[c + 1];
                if (row0 < N)
                    *(float2*)&out[(long)row0 * 64 + c] = make_float2(a0.f.x + bx, a1.f.x + by);
                if (row1 < N)
                    *(float2*)&out[(long)row1 * 64 + c] = make_float2(a0.f.y + bx, a1.f.y + by);
            } else {
                if (row0 < N) {
                    float2 o = make_float2(d0 * a0.f.x, d0 * a1.f.x);
                    *(float2*)&g[(long)row0 * 64 + c] = o;
                    *(float2*)&s[(long)row0 * 64 + c] = o;
                }
                if (row1 < N) {
                    float2 o = make_float2(d1 * a0.f.y, d1 * a1.f.y);
                    *(float2*)&g[(long)row1 * 64 + c] = o;
                    *(float2*)&s[(long)row1 * 64 + c] = o;
                }
            }
        }
    }
}

// ---------------------------------------------------------------------------
// Scatter: 16 lanes per edge, LDG.128 + red.global.add.v4.f32
// ---------------------------------------------------------------------------
__global__ void __launch_bounds__(256)
scatter2_kernel(const int* __restrict__ row, const int* __restrict__ col,
                const float* __restrict__ g, float* __restrict__ s, int e)
{
    int gt   = blockIdx.x * blockDim.x + threadIdx.x;
    int eidx = gt >> 4;
    int sub  = gt & 15;
    if (eidx >= e) return;
    int r = __ldg(&row[eidx]);
    int c = __ldg(&col[eidx]);
    float4 v = __ldg((const float4*)&g[(long)r * 64 + sub * 4]);
    float* dst = &s[(long)c * 64 + sub * 4];
    asm volatile("red.global.add.v4.f32 [%0], {%1,%2,%3,%4};"
                 :: "l"(dst), "f"(v.x), "f"(v.y), "f"(v.z), "f"(v.w)
                 : "memory");
}

// ---------------------------------------------------------------------------
extern "C" void kernel_launch(void* const* d_in, const int* in_sizes, int n_in,
                              void* d_out, int out_size)
{
    const int*   user_ids   = (const int*)  d_in[0];
    const int*   item_ids   = (const int*)  d_in[1];
    const int*   edge_index = (const int*)  d_in[2];
    const float* user_table = (const float*)d_in[4];
    const float* item_table = (const float*)d_in[5];
    const float* W1 = (const float*)d_in[6];
    const float* b1 = (const float*)d_in[7];
    const float* W2 = (const float*)d_in[8];
    const float* b2 = (const float*)d_in[9];
    const float* W3 = (const float*)d_in[10];
    const float* b3 = (const float*)d_in[11];
    const float* lin_W = (const float*)d_in[12];
    const float* lin_b = (const float*)d_in[13];
    float* out = (float*)d_out;

    const int U = in_sizes[0];
    const int I = in_sizes[1];
    const int N = U + I;
    const int E = in_sizes[2] / 2;
    const int* erow = edge_index;
    const int* ecol = edge_index + E;

    float *g, *s, *deg, *dinv;
    cudaGetSymbolAddress((void**)&g,    d_g);
    cudaGetSymbolAddress((void**)&s,    d_s);
    cudaGetSymbolAddress((void**)&deg,  d_deg);
    cudaGetSymbolAddress((void**)&dinv, d_dinv);

    const size_t smemB = SMEM_FLOATS * sizeof(float);
    static bool attrSet = false;
    if (!attrSet) {
        cudaFuncSetAttribute(mm5_kernel<0>, cudaFuncAttributeMaxDynamicSharedMemorySize, (int)smemB);
        cudaFuncSetAttribute(mm5_kernel<1>, cudaFuncAttributeMaxDynamicSharedMemorySize, (int)smemB);
        cudaFuncSetAttribute(mm5_kernel<2>, cudaFuncAttributeMaxDynamicSharedMemorySize, (int)smemB);
        attrSet = true;
    }

    const int mmBlocks = (N + BR - 1) / BR;
    const int scBlocks = (E * 16 + 255) / 256;
    const int nB = (N + 255) / 256;
    const int eB = (E + 255) / 256;

    deg_init_kernel<<<nB, 256>>>(deg, N);
    deg_count_kernel<<<eB, 256>>>(ecol, deg, E);
    dinv_kernel<<<nB, 256>>>(deg, dinv, N);

    mm5_kernel<0><<<mmBlocks, 256, smemB>>>(user_table, item_table, user_ids, item_ids,
                                            dinv, nullptr, W1, nullptr, g, s, nullptr, N, U);
    scatter2_kernel<<<scBlocks, 256>>>(erow, ecol, g, s, E);

    mm5_kernel<1><<<mmBlocks, 256, smemB>>>(s, nullptr, nullptr, nullptr,
                                            dinv, b1, W2, nullptr, g, s, nullptr, N, U);
    scatter2_kernel<<<scBlocks, 256>>>(erow, ecol, g, s, E);

    mm5_kernel<1><<<mmBlocks, 256, smemB>>>(s, nullptr, nullptr, nullptr,
                                            dinv, b2, W3, nullptr, g, s, nullptr, N, U);
    scatter2_kernel<<<scBlocks, 256>>>(erow, ecol, g, s, E);

    mm5_kernel<2><<<mmBlocks, 256, smemB>>>(s, nullptr, nullptr, nullptr,
                                            dinv, b3, lin_W, lin_b, nullptr, nullptr, out, N, U);
}